// round 2
// baseline (speedup 1.0000x reference)
#include <cuda_runtime.h>
#include <math.h>

#define BATCH 4
#define NQ    2048
#define DIM   1024
#define HEADS 16
#define HD    64
#define M_ROWS (BATCH*NQ)     // 8192
#define N_COLS (3*DIM)        // 3072
#define K_DIM  DIM            // 1024
#define QKV_SECT ((size_t)BATCH*HEADS*NQ*HD)   // 8388608 floats per section

// scratch for Q,K,V in [which][b*h][n][d] layout
__device__ float g_qkv[3ull * BATCH * HEADS * NQ * HD];

// ---------------------------------------------------------------------------
// Kernel 1: qkv = x @ W + b, fused partial-interleaved RoPE on q,k, scatter
// into g_qkv laid out [which][b][h][n][d].
// Block tile 128x128, BK=16, 256 threads, 8x8 microtile.
// ---------------------------------------------------------------------------
#define GBM 128
#define GBN 128
#define GBK 16

__global__ __launch_bounds__(256) void qkv_gemm_rope(
    const float* __restrict__ X, const float* __restrict__ W,
    const float* __restrict__ bias)
{
    __shared__ float As[GBK][GBM + 4];   // transposed: As[k][row]
    __shared__ float Bs[GBK][GBN];       // Bs[k][col]

    const int tid  = threadIdx.x;
    const int row0 = blockIdx.y * GBM;
    const int col0 = blockIdx.x * GBN;
    const int tr = tid >> 4;    // 0..15
    const int tc = tid & 15;    // 0..15

    float acc[8][8];
#pragma unroll
    for (int i = 0; i < 8; i++)
#pragma unroll
        for (int j = 0; j < 8; j++) acc[i][j] = 0.f;

    const int arow = tid >> 1;          // 0..127
    const int ak   = (tid & 1) * 8;     // 0 or 8
    const int brow = tid >> 4;          // 0..15
    const int bcol = (tid & 15) * 8;    // 0..120

    const float* Ag = X + (size_t)(row0 + arow) * K_DIM + ak;
    const float* Bg = W + (size_t)brow * N_COLS + col0 + bcol;

    for (int k0 = 0; k0 < K_DIM; k0 += GBK) {
        float4 a0 = *(const float4*)(Ag + k0);
        float4 a1 = *(const float4*)(Ag + k0 + 4);
        float4 b0 = *(const float4*)(Bg + (size_t)k0 * N_COLS);
        float4 b1 = *(const float4*)(Bg + (size_t)k0 * N_COLS + 4);

        As[ak + 0][arow] = a0.x;  As[ak + 1][arow] = a0.y;
        As[ak + 2][arow] = a0.z;  As[ak + 3][arow] = a0.w;
        As[ak + 4][arow] = a1.x;  As[ak + 5][arow] = a1.y;
        As[ak + 6][arow] = a1.z;  As[ak + 7][arow] = a1.w;
        *(float4*)&Bs[brow][bcol]     = b0;
        *(float4*)&Bs[brow][bcol + 4] = b1;
        __syncthreads();

#pragma unroll
        for (int k = 0; k < GBK; k++) {
            float a[8], b[8];
            *(float4*)&a[0] = *(const float4*)&As[k][tr * 8];
            *(float4*)&a[4] = *(const float4*)&As[k][tr * 8 + 4];
            *(float4*)&b[0] = *(const float4*)&Bs[k][tc * 8];
            *(float4*)&b[4] = *(const float4*)&Bs[k][tc * 8 + 4];
#pragma unroll
            for (int i = 0; i < 8; i++)
#pragma unroll
                for (int j = 0; j < 8; j++) acc[i][j] += a[i] * b[j];
        }
        __syncthreads();
    }

    // ---- epilogue: bias + RoPE + scatter ----
    const int gcol   = col0 + tc * 8;          // global col, 8-aligned
    const int which  = gcol >> 10;             // 0=q,1=k,2=v
    const int within = gcol & 1023;
    const int head   = within >> 6;
    const int dcb    = within & 63;            // 8-aligned dim base within head

    float bv[8];
#pragma unroll
    for (int j = 0; j < 8; j++) bv[j] = bias[gcol + j];

    const bool do_rope = (which < 2) && (dcb < 32);
    float invf[4];
    if (do_rope) {
#pragma unroll
        for (int jj = 0; jj < 4; jj++) {
            int pj = (dcb >> 1) + jj;   // pair index 0..15
            // inv_freq = 10000^(-pj/16), computed in double for accuracy
            invf[jj] = (float)exp(-(double)pj * (log(10000.0) / 16.0));
        }
    }

#pragma unroll
    for (int i = 0; i < 8; i++) {
        const int row   = row0 + tr * 8 + i;
        const int batch = row >> 11;
        const int pos   = row & 2047;
        float v[8];
#pragma unroll
        for (int j = 0; j < 8; j++) v[j] = acc[i][j] + bv[j];
        if (do_rope) {
            const float fp = (float)pos;
#pragma unroll
            for (int jj = 0; jj < 4; jj++) {
                float ang = fp * invf[jj];
                float s, c;
                sincosf(ang, &s, &c);
                float x = v[2 * jj], y = v[2 * jj + 1];
                v[2 * jj]     = x * c - y * s;
                v[2 * jj + 1] = y * c + x * s;
            }
        }
        size_t dst = (size_t)which * QKV_SECT
                   + (((size_t)(batch * HEADS + head)) * NQ + pos) * HD + dcb;
        *(float4*)(g_qkv + dst)     = make_float4(v[0], v[1], v[2], v[3]);
        *(float4*)(g_qkv + dst + 4) = make_float4(v[4], v[5], v[6], v[7]);
    }
}

// ---------------------------------------------------------------------------
// Kernel 2: flash attention, fp32. Per CTA: 64 q rows of one (b,h);
// loop over 32 key tiles of 64. 256 threads, 4x4 microtiles.
// smem: QsT[d][row], KsT[d][key] (d-major => conflict-free float4 reads),
//       Vs[key][d], Ps[row][key]. Total 64 KB.
// ---------------------------------------------------------------------------
__global__ __launch_bounds__(256) void attn_kernel(float* __restrict__ out)
{
    extern __shared__ float sm[];
    float* QsT = sm;                 // [64][64]
    float* KsT = sm + 64 * 64;       // [64][64]
    float* Vs  = sm + 2 * 64 * 64;   // [64][64]
    float* Ps  = sm + 3 * 64 * 64;   // [64][64]

    const int tid = threadIdx.x;
    const int tr = tid >> 4;         // 0..15
    const int tc = tid & 15;         // 0..15
    const int r0 = tr * 4;           // local q row base
    const int c0 = tc * 4;           // local key / out-dim base

    const int bh    = blockIdx.y;
    const int qrow0 = blockIdx.x * 64;

    const size_t bhoff = (size_t)bh * NQ * HD;
    const float* Qg = g_qkv + bhoff;
    const float* Kg = g_qkv + QKV_SECT + bhoff;
    const float* Vg = g_qkv + 2 * QKV_SECT + bhoff;

    // load Q tile transposed + pre-scaled by 1/sqrt(d)
    {
        const int lrow = tid >> 2;            // 0..63
        const int lk   = (tid & 3) * 16;
        const float* src = Qg + (size_t)(qrow0 + lrow) * HD + lk;
#pragma unroll
        for (int j = 0; j < 4; j++) {
            float4 q = *(const float4*)(src + 4 * j);
            QsT[(lk + 4 * j + 0) * 64 + lrow] = q.x * 0.125f;
            QsT[(lk + 4 * j + 1) * 64 + lrow] = q.y * 0.125f;
            QsT[(lk + 4 * j + 2) * 64 + lrow] = q.z * 0.125f;
            QsT[(lk + 4 * j + 3) * 64 + lrow] = q.w * 0.125f;
        }
    }

    float m[4], l[4], acc[4][4];
#pragma unroll
    for (int i = 0; i < 4; i++) {
        m[i] = -INFINITY; l[i] = 0.f;
#pragma unroll
        for (int j = 0; j < 4; j++) acc[i][j] = 0.f;
    }
    __syncthreads();

    for (int kt = 0; kt < NQ / 64; kt++) {
        // load K (transposed) and V (natural)
        {
            const int lrow = tid >> 2;
            const int lk   = (tid & 3) * 16;
            const float* ks = Kg + (size_t)(kt * 64 + lrow) * HD + lk;
            const float* vs = Vg + (size_t)(kt * 64 + lrow) * HD + lk;
#pragma unroll
            for (int j = 0; j < 4; j++) {
                float4 kv = *(const float4*)(ks + 4 * j);
                KsT[(lk + 4 * j + 0) * 64 + lrow] = kv.x;
                KsT[(lk + 4 * j + 1) * 64 + lrow] = kv.y;
                KsT[(lk + 4 * j + 2) * 64 + lrow] = kv.z;
                KsT[(lk + 4 * j + 3) * 64 + lrow] = kv.w;
                *(float4*)&Vs[lrow * 64 + lk + 4 * j] = *(const float4*)(vs + 4 * j);
            }
        }
        __syncthreads();

        // S = Q K^T (scaled)
        float s[4][4];
#pragma unroll
        for (int i = 0; i < 4; i++)
#pragma unroll
            for (int j = 0; j < 4; j++) s[i][j] = 0.f;
#pragma unroll 16
        for (int k = 0; k < 64; k++) {
            float4 q = *(const float4*)&QsT[k * 64 + r0];
            float4 kk = *(const float4*)&KsT[k * 64 + c0];
            float qa[4] = {q.x, q.y, q.z, q.w};
            float ka[4] = {kk.x, kk.y, kk.z, kk.w};
#pragma unroll
            for (int i = 0; i < 4; i++)
#pragma unroll
                for (int j = 0; j < 4; j++) s[i][j] += qa[i] * ka[j];
        }

        // online softmax (row reductions across the 16 tc lanes)
        float mt[4], rs[4], alpha[4];
#pragma unroll
        for (int i = 0; i < 4; i++) {
            mt[i] = fmaxf(fmaxf(s[i][0], s[i][1]), fmaxf(s[i][2], s[i][3]));
#pragma unroll
            for (int off = 8; off; off >>= 1)
                mt[i] = fmaxf(mt[i], __shfl_xor_sync(0xffffffffu, mt[i], off));
            float mn = fmaxf(m[i], mt[i]);
            alpha[i] = __expf(m[i] - mn);
            m[i] = mn;
#pragma unroll
            for (int j = 0; j < 4; j++) s[i][j] = __expf(s[i][j] - mn);
            rs[i] = s[i][0] + s[i][1] + s[i][2] + s[i][3];
#pragma unroll
            for (int off = 8; off; off >>= 1)
                rs[i] += __shfl_xor_sync(0xffffffffu, rs[i], off);
            l[i] = l[i] * alpha[i] + rs[i];
#pragma unroll
            for (int j = 0; j < 4; j++) acc[i][j] *= alpha[i];
            // stash probabilities
            *(float4*)&Ps[(r0 + i) * 64 + c0] = make_float4(s[i][0], s[i][1], s[i][2], s[i][3]);
        }
        __syncthreads();

        // O += P @ V
#pragma unroll 16
        for (int k = 0; k < 64; k++) {
            float4 vv = *(const float4*)&Vs[k * 64 + c0];
            float va[4] = {vv.x, vv.y, vv.z, vv.w};
            float p0 = Ps[(r0 + 0) * 64 + k];
            float p1 = Ps[(r0 + 1) * 64 + k];
            float p2 = Ps[(r0 + 2) * 64 + k];
            float p3 = Ps[(r0 + 3) * 64 + k];
#pragma unroll
            for (int j = 0; j < 4; j++) {
                acc[0][j] += p0 * va[j];
                acc[1][j] += p1 * va[j];
                acc[2][j] += p2 * va[j];
                acc[3][j] += p3 * va[j];
            }
        }
        __syncthreads();
    }

    // finalize: divide by l, write out[b][pos][head*64 + d]
    const int batch = bh >> 4;
    const int head  = bh & 15;
#pragma unroll
    for (int i = 0; i < 4; i++) {
        float inv = 1.f / l[i];
        int pos = qrow0 + r0 + i;
        float4 o = make_float4(acc[i][0] * inv, acc[i][1] * inv,
                               acc[i][2] * inv, acc[i][3] * inv);
        *(float4*)(out + ((size_t)(batch * NQ + pos)) * DIM + head * HD + c0) = o;
    }
}

// ---------------------------------------------------------------------------
extern "C" void kernel_launch(void* const* d_in, const int* in_sizes, int n_in,
                              void* d_out, int out_size)
{
    const float* x = (const float*)d_in[0];
    const float* w = (const float*)d_in[1];
    const float* b = (const float*)d_in[2];
    float* out = (float*)d_out;

    dim3 g1(N_COLS / GBN, M_ROWS / GBM);   // (24, 64)
    qkv_gemm_rope<<<g1, 256>>>(x, w, b);

    int smem = 4 * 64 * 64 * (int)sizeof(float);  // 64 KB
    cudaFuncSetAttribute(attn_kernel, cudaFuncAttributeMaxDynamicSharedMemorySize, smem);
    dim3 g2(NQ / 64, BATCH * HEADS);       // (32, 64)
    attn_kernel<<<g2, 256, smem>>>(out);
}

// round 4
// speedup vs baseline: 1.2752x; 1.2752x over previous
#include <cuda_runtime.h>
#include <cuda_bf16.h>
#include <math.h>

#define BATCH 4
#define NQ    2048
#define DIM   1024
#define HEADS 16
#define HD    64
#define M_ROWS (BATCH*NQ)     // 8192
#define N_COLS (3*DIM)        // 3072
#define K_DIM  DIM            // 1024
#define QKV_SECT ((size_t)BATCH*HEADS*NQ*HD)

// scratch for Q,K,V in [which][b*h][n][d] fp32 layout
__device__ float g_qkv[3ull * BATCH * HEADS * NQ * HD];

// ---------------------------------------------------------------------------
// Kernel 1: qkv = x @ W + b on tensor cores (bf16 hi/lo split, 3 MMA passes),
// fused RoPE + scatter epilogue. CTA tile 128x128, k-chunk 32, 8 warps.
// ---------------------------------------------------------------------------
#define BM 128
#define BN 128
#define BK 32
#define SPAD 42   // bf16 elements per smem row (BK + 10): odd-word stride

__device__ __forceinline__ void cvt_hilo(float x, __nv_bfloat16& h, __nv_bfloat16& l) {
    h = __float2bfloat16_rn(x);
    l = __float2bfloat16_rn(x - __bfloat162float(h));
}

#define MMA_BF16(C, A, B) \
    asm volatile("mma.sync.aligned.m16n8k16.row.col.f32.bf16.bf16.f32 " \
                 "{%0,%1,%2,%3}, {%4,%5,%6,%7}, {%8,%9}, {%0,%1,%2,%3};\n" \
                 : "+f"((C)[0]), "+f"((C)[1]), "+f"((C)[2]), "+f"((C)[3]) \
                 : "r"((A)[0]), "r"((A)[1]), "r"((A)[2]), "r"((A)[3]), \
                   "r"((B)[0]), "r"((B)[1]))

__global__ __launch_bounds__(256, 1) void qkv_gemm_rope(
    const float* __restrict__ X, const float* __restrict__ W,
    const float* __restrict__ bias)
{
    __shared__ __nv_bfloat16 As_hi[BM][SPAD];
    __shared__ __nv_bfloat16 As_lo[BM][SPAD];
    __shared__ __nv_bfloat16 Bs_hi[BN][SPAD];   // [n][k]
    __shared__ __nv_bfloat16 Bs_lo[BN][SPAD];

    const int tid  = threadIdx.x;
    const int lane = tid & 31;
    const int wid  = tid >> 5;
    const int row0 = blockIdx.y * BM;
    const int col0 = blockIdx.x * BN;
    const int wr = (wid >> 2) * 64;   // warp row offset in tile
    const int wc = (wid & 3) * 32;    // warp col offset in tile
    const int g  = lane >> 2;         // groupID 0..7
    const int tg = lane & 3;          // thread-in-group

    float c[4][4][4];
#pragma unroll
    for (int mt = 0; mt < 4; mt++)
#pragma unroll
        for (int nt = 0; nt < 4; nt++)
#pragma unroll
            for (int e = 0; e < 4; e++) c[mt][nt][e] = 0.f;

    // global load mapping
    const int arow = tid >> 1;            // 0..127
    const int acb  = (tid & 1) * 16;      // 0 or 16 (k offset)
    const int bk0  = (tid >> 4) * 2;      // 0..30 (k row, even)
    const int bnb  = (tid & 15) * 8;      // 0..120 (n offset)

    const float* Ag = X + (size_t)(row0 + arow) * K_DIM + acb;
    const float* Bg = W + (size_t)bk0 * N_COLS + col0 + bnb;

    float4 abuf[4], bbuf[4];
#define LOADA(kk) { abuf[0] = *(const float4*)(Ag + (kk));      \
                    abuf[1] = *(const float4*)(Ag + (kk) + 4);  \
                    abuf[2] = *(const float4*)(Ag + (kk) + 8);  \
                    abuf[3] = *(const float4*)(Ag + (kk) + 12); }
#define LOADB(kk) { const float* p = Bg + (size_t)(kk) * N_COLS; \
                    bbuf[0] = *(const float4*)p;                  \
                    bbuf[1] = *(const float4*)(p + 4);            \
                    bbuf[2] = *(const float4*)(p + N_COLS);       \
                    bbuf[3] = *(const float4*)(p + N_COLS + 4); }

    LOADA(0); LOADB(0);

    for (int k0 = 0; k0 < K_DIM; k0 += BK) {
        // convert + store staged tile to smem
        {
            const float* af = (const float*)abuf;
#pragma unroll
            for (int e = 0; e < 16; e += 2) {
                __nv_bfloat16 h0, l0, h1, l1;
                cvt_hilo(af[e], h0, l0);
                cvt_hilo(af[e + 1], h1, l1);
                __nv_bfloat162 ph; ph.x = h0; ph.y = h1;
                __nv_bfloat162 pl; pl.x = l0; pl.y = l1;
                *(__nv_bfloat162*)&As_hi[arow][acb + e] = ph;
                *(__nv_bfloat162*)&As_lo[arow][acb + e] = pl;
            }
            const float* bf = (const float*)bbuf;
#pragma unroll
            for (int j = 0; j < 8; j++) {
                __nv_bfloat16 h0, l0, h1, l1;
                cvt_hilo(bf[j], h0, l0);        // k = bk0
                cvt_hilo(bf[8 + j], h1, l1);    // k = bk0+1
                __nv_bfloat162 ph; ph.x = h0; ph.y = h1;
                __nv_bfloat162 pl; pl.x = l0; pl.y = l1;
                *(__nv_bfloat162*)&Bs_hi[bnb + j][bk0] = ph;
                *(__nv_bfloat162*)&Bs_lo[bnb + j][bk0] = pl;
            }
        }
        __syncthreads();

        if (k0 + BK < K_DIM) { LOADA(k0 + BK); LOADB(k0 + BK); }

#pragma unroll
        for (int ks = 0; ks < 2; ks++) {
            const int kk = ks * 16 + 2 * tg;
            unsigned ah[4][4], al[4][4], bh[4][2], bl[4][2];
#pragma unroll
            for (int mt = 0; mt < 4; mt++) {
                const int r = wr + mt * 16 + g;
                ah[mt][0] = *(const unsigned*)&As_hi[r][kk];
                ah[mt][1] = *(const unsigned*)&As_hi[r + 8][kk];
                ah[mt][2] = *(const unsigned*)&As_hi[r][kk + 8];
                ah[mt][3] = *(const unsigned*)&As_hi[r + 8][kk + 8];
                al[mt][0] = *(const unsigned*)&As_lo[r][kk];
                al[mt][1] = *(const unsigned*)&As_lo[r + 8][kk];
                al[mt][2] = *(const unsigned*)&As_lo[r][kk + 8];
                al[mt][3] = *(const unsigned*)&As_lo[r + 8][kk + 8];
            }
#pragma unroll
            for (int nt = 0; nt < 4; nt++) {
                const int n = wc + nt * 8 + g;
                bh[nt][0] = *(const unsigned*)&Bs_hi[n][kk];
                bh[nt][1] = *(const unsigned*)&Bs_hi[n][kk + 8];
                bl[nt][0] = *(const unsigned*)&Bs_lo[n][kk];
                bl[nt][1] = *(const unsigned*)&Bs_lo[n][kk + 8];
            }
#pragma unroll
            for (int mt = 0; mt < 4; mt++)
#pragma unroll
                for (int nt = 0; nt < 4; nt++) {
                    MMA_BF16(c[mt][nt], ah[mt], bh[nt]);
                    MMA_BF16(c[mt][nt], ah[mt], bl[nt]);
                    MMA_BF16(c[mt][nt], al[mt], bh[nt]);
                }
        }
        __syncthreads();
    }

    // ---- epilogue: bias + RoPE + scatter (cols come as adjacent pairs) ----
#pragma unroll
    for (int nt = 0; nt < 4; nt++) {
        const int col    = col0 + wc + nt * 8 + 2 * tg;   // even
        const int which  = col >> 10;
        const int within = col & 1023;
        const int head   = within >> 6;
        const int dc     = within & 63;                   // even
        const float b0v = bias[col], b1v = bias[col + 1];
        const bool rope = (which < 2) && (dc < 32);
        float invf = 0.f;
        if (rope) invf = (float)exp(-(double)(dc >> 1) * (log(10000.0) / 16.0));
#pragma unroll
        for (int mt = 0; mt < 4; mt++) {
#pragma unroll
            for (int rr = 0; rr < 2; rr++) {
                const int row   = row0 + wr + mt * 16 + g + rr * 8;
                const int batch = row >> 11;
                const int pos   = row & 2047;
                float v0 = c[mt][nt][rr * 2 + 0] + b0v;
                float v1 = c[mt][nt][rr * 2 + 1] + b1v;
                if (rope) {
                    float s, co;
                    sincosf((float)pos * invf, &s, &co);
                    float x = v0, y = v1;
                    v0 = x * co - y * s;
                    v1 = y * co + x * s;
                }
                size_t dst = (size_t)which * QKV_SECT
                           + (((size_t)(batch * HEADS + head)) * NQ + pos) * HD + dc;
                *(float2*)(g_qkv + dst) = make_float2(v0, v1);
            }
        }
    }
}

// ---------------------------------------------------------------------------
// Kernel 2: flash attention, fp32 SIMT. Tile 128 q-rows x 64 keys, 256 thr,
// 8x4 microtiles. smem ~98KB -> 2 CTAs/SM.
// ---------------------------------------------------------------------------
#define PADP 68

__global__ __launch_bounds__(256, 2) void attn_kernel(float* __restrict__ out)
{
    extern __shared__ float sm[];
    float* QsT = sm;                       // [64][128] d-major
    float* KsT = sm + 64 * 128;            // [64][64]  d-major
    float* Vs  = KsT + 64 * 64;            // [64][64]  key-major
    float* Ps  = Vs + 64 * 64;             // [128][PADP]

    const int tid = threadIdx.x;
    const int tr = tid >> 4;               // 0..15
    const int tc = tid & 15;               // 0..15
    const int r0 = tr * 8;                 // 8 q rows
    const int c0 = tc * 4;                 // 4 keys / out dims

    const int bh = blockIdx.y;
    const int q0 = blockIdx.x * 128;

    const size_t bhoff = (size_t)bh * NQ * HD;
    const float* Qg = g_qkv + bhoff;
    const float* Kg = g_qkv + QKV_SECT + bhoff;
    const float* Vg = g_qkv + 2 * QKV_SECT + bhoff;

    // load Q tile transposed + pre-scaled
    {
        const int lrow = tid >> 1;             // 0..127
        const int ldb  = (tid & 1) * 32;
        const float* src = Qg + (size_t)(q0 + lrow) * HD + ldb;
#pragma unroll
        for (int j = 0; j < 8; j++) {
            float4 q = *(const float4*)(src + 4 * j);
            QsT[(ldb + 4 * j + 0) * 128 + lrow] = q.x * 0.125f;
            QsT[(ldb + 4 * j + 1) * 128 + lrow] = q.y * 0.125f;
            QsT[(ldb + 4 * j + 2) * 128 + lrow] = q.z * 0.125f;
            QsT[(ldb + 4 * j + 3) * 128 + lrow] = q.w * 0.125f;
        }
    }

    float m[8], l[8], acc[8][4];
#pragma unroll
    for (int i = 0; i < 8; i++) {
        m[i] = -INFINITY; l[i] = 0.f;
#pragma unroll
        for (int j = 0; j < 4; j++) acc[i][j] = 0.f;
    }
    __syncthreads();

    for (int kt = 0; kt < NQ / 64; kt++) {
        {
            const int lrow = tid >> 2;
            const int ld   = (tid & 3) * 16;
            const float* ks = Kg + (size_t)(kt * 64 + lrow) * HD + ld;
            const float* vs = Vg + (size_t)(kt * 64 + lrow) * HD + ld;
#pragma unroll
            for (int j = 0; j < 4; j++) {
                float4 kv = *(const float4*)(ks + 4 * j);
                KsT[(ld + 4 * j + 0) * 64 + lrow] = kv.x;
                KsT[(ld + 4 * j + 1) * 64 + lrow] = kv.y;
                KsT[(ld + 4 * j + 2) * 64 + lrow] = kv.z;
                KsT[(ld + 4 * j + 3) * 64 + lrow] = kv.w;
                *(float4*)&Vs[lrow * 64 + ld + 4 * j] = *(const float4*)(vs + 4 * j);
            }
        }
        __syncthreads();

        // S = Q K^T
        float s[8][4];
#pragma unroll
        for (int i = 0; i < 8; i++)
#pragma unroll
            for (int j = 0; j < 4; j++) s[i][j] = 0.f;
#pragma unroll 8
        for (int d = 0; d < 64; d++) {
            float4 qa = *(const float4*)&QsT[d * 128 + r0];
            float4 qb = *(const float4*)&QsT[d * 128 + r0 + 4];
            float4 kk = *(const float4*)&KsT[d * 64 + c0];
            float qv[8] = {qa.x, qa.y, qa.z, qa.w, qb.x, qb.y, qb.z, qb.w};
            float kv[4] = {kk.x, kk.y, kk.z, kk.w};
#pragma unroll
            for (int i = 0; i < 8; i++)
#pragma unroll
                for (int j = 0; j < 4; j++) s[i][j] += qv[i] * kv[j];
        }

        // online softmax (rows reduced over the 16 tc lanes)
#pragma unroll
        for (int i = 0; i < 8; i++) {
            float mt = fmaxf(fmaxf(s[i][0], s[i][1]), fmaxf(s[i][2], s[i][3]));
#pragma unroll
            for (int off = 8; off; off >>= 1)
                mt = fmaxf(mt, __shfl_xor_sync(0xffffffffu, mt, off));
            float mn = fmaxf(m[i], mt);
            float alpha = __expf(m[i] - mn);
            m[i] = mn;
#pragma unroll
            for (int j = 0; j < 4; j++) s[i][j] = __expf(s[i][j] - mn);
            float rs = s[i][0] + s[i][1] + s[i][2] + s[i][3];
#pragma unroll
            for (int off = 8; off; off >>= 1)
                rs += __shfl_xor_sync(0xffffffffu, rs, off);
            l[i] = l[i] * alpha + rs;
#pragma unroll
            for (int j = 0; j < 4; j++) acc[i][j] *= alpha;
            *(float4*)&Ps[(r0 + i) * PADP + c0] = make_float4(s[i][0], s[i][1], s[i][2], s[i][3]);
        }
        __syncthreads();

        // O += P @ V
#pragma unroll 8
        for (int k = 0; k < 64; k++) {
            float4 vv = *(const float4*)&Vs[k * 64 + c0];
            float va[4] = {vv.x, vv.y, vv.z, vv.w};
#pragma unroll
            for (int i = 0; i < 8; i++) {
                float p = Ps[(r0 + i) * PADP + k];
#pragma unroll
                for (int j = 0; j < 4; j++) acc[i][j] += p * va[j];
            }
        }
        __syncthreads();
    }

    // finalize
    const int batch = bh >> 4;
    const int head  = bh & 15;
#pragma unroll
    for (int i = 0; i < 8; i++) {
        float inv = 1.f / l[i];
        int pos = q0 + r0 + i;
        float4 o = make_float4(acc[i][0] * inv, acc[i][1] * inv,
                               acc[i][2] * inv, acc[i][3] * inv);
        *(float4*)(out + ((size_t)(batch * NQ + pos)) * DIM + head * HD + c0) = o;
    }
}

// ---------------------------------------------------------------------------
extern "C" void kernel_launch(void* const* d_in, const int* in_sizes, int n_in,
                              void* d_out, int out_size)
{
    const float* x = (const float*)d_in[0];
    const float* w = (const float*)d_in[1];
    const float* b = (const float*)d_in[2];
    float* out = (float*)d_out;

    dim3 g1(N_COLS / BN, M_ROWS / BM);    // (24, 64)
    qkv_gemm_rope<<<g1, 256>>>(x, w, b);

    int smem = (64 * 128 + 64 * 64 + 64 * 64 + 128 * PADP) * (int)sizeof(float);
    cudaFuncSetAttribute(attn_kernel, cudaFuncAttributeMaxDynamicSharedMemorySize, smem);
    dim3 g2(NQ / 128, BATCH * HEADS);     // (16, 64)
    attn_kernel<<<g2, 256, smem>>>(out);
}

// round 5
// speedup vs baseline: 1.8867x; 1.4796x over previous
#include <cuda_runtime.h>
#include <cuda_bf16.h>
#include <math.h>

#define BATCH 4
#define NQ    2048
#define DIM   1024
#define HEADS 16
#define HD    64
#define M_ROWS (BATCH*NQ)
#define N_COLS (3*DIM)
#define K_DIM  DIM
#define BHND ((size_t)BATCH*HEADS*NQ*HD)

// bf16 hi/lo planes. Q,K: [bh][n][d]. V: transposed [bh][d][n].
__device__ __nv_bfloat16 g_q_hi[BHND], g_q_lo[BHND];
__device__ __nv_bfloat16 g_k_hi[BHND], g_k_lo[BHND];
__device__ __nv_bfloat16 g_vt_hi[BHND], g_vt_lo[BHND];

__device__ __forceinline__ void cvt_hilo(float x, __nv_bfloat16& h, __nv_bfloat16& l) {
    h = __float2bfloat16_rn(x);
    l = __float2bfloat16_rn(x - __bfloat162float(h));
}

#define MMA_BF16(C, A, B) \
    asm volatile("mma.sync.aligned.m16n8k16.row.col.f32.bf16.bf16.f32 " \
                 "{%0,%1,%2,%3}, {%4,%5,%6,%7}, {%8,%9}, {%0,%1,%2,%3};\n" \
                 : "+f"((C)[0]), "+f"((C)[1]), "+f"((C)[2]), "+f"((C)[3]) \
                 : "r"((A)[0]), "r"((A)[1]), "r"((A)[2]), "r"((A)[3]), \
                   "r"((B)[0]), "r"((B)[1]))

// ---------------------------------------------------------------------------
// Kernel 1: qkv = x @ W + b (bf16 hi/lo, 3-pass MMA), RoPE, scatter to planes.
// ---------------------------------------------------------------------------
#define BM 128
#define BN 128
#define BK 32
#define SPAD 42

__global__ __launch_bounds__(256, 1) void qkv_gemm_rope(
    const float* __restrict__ X, const float* __restrict__ W,
    const float* __restrict__ bias)
{
    __shared__ __nv_bfloat16 As_hi[BM][SPAD];
    __shared__ __nv_bfloat16 As_lo[BM][SPAD];
    __shared__ __nv_bfloat16 Bs_hi[BN][SPAD];
    __shared__ __nv_bfloat16 Bs_lo[BN][SPAD];

    const int tid  = threadIdx.x;
    const int lane = tid & 31;
    const int wid  = tid >> 5;
    const int row0 = blockIdx.y * BM;
    const int col0 = blockIdx.x * BN;
    const int wr = (wid >> 2) * 64;
    const int wc = (wid & 3) * 32;
    const int g  = lane >> 2;
    const int tg = lane & 3;

    float c[4][4][4];
#pragma unroll
    for (int mt = 0; mt < 4; mt++)
#pragma unroll
        for (int nt = 0; nt < 4; nt++)
#pragma unroll
            for (int e = 0; e < 4; e++) c[mt][nt][e] = 0.f;

    const int arow = tid >> 1;
    const int acb  = (tid & 1) * 16;
    const int bk0  = (tid >> 4) * 2;
    const int bnb  = (tid & 15) * 8;

    const float* Ag = X + (size_t)(row0 + arow) * K_DIM + acb;
    const float* Bg = W + (size_t)bk0 * N_COLS + col0 + bnb;

    float4 abuf[4], bbuf[4];
#define LOADA(kk) { abuf[0] = *(const float4*)(Ag + (kk));      \
                    abuf[1] = *(const float4*)(Ag + (kk) + 4);  \
                    abuf[2] = *(const float4*)(Ag + (kk) + 8);  \
                    abuf[3] = *(const float4*)(Ag + (kk) + 12); }
#define LOADB(kk) { const float* p = Bg + (size_t)(kk) * N_COLS; \
                    bbuf[0] = *(const float4*)p;                  \
                    bbuf[1] = *(const float4*)(p + 4);            \
                    bbuf[2] = *(const float4*)(p + N_COLS);       \
                    bbuf[3] = *(const float4*)(p + N_COLS + 4); }

    LOADA(0); LOADB(0);

    for (int k0 = 0; k0 < K_DIM; k0 += BK) {
        {
            const float* af = (const float*)abuf;
#pragma unroll
            for (int e = 0; e < 16; e += 2) {
                __nv_bfloat16 h0, l0, h1, l1;
                cvt_hilo(af[e], h0, l0);
                cvt_hilo(af[e + 1], h1, l1);
                __nv_bfloat162 ph; ph.x = h0; ph.y = h1;
                __nv_bfloat162 pl; pl.x = l0; pl.y = l1;
                *(__nv_bfloat162*)&As_hi[arow][acb + e] = ph;
                *(__nv_bfloat162*)&As_lo[arow][acb + e] = pl;
            }
            const float* bf = (const float*)bbuf;
#pragma unroll
            for (int j = 0; j < 8; j++) {
                __nv_bfloat16 h0, l0, h1, l1;
                cvt_hilo(bf[j], h0, l0);
                cvt_hilo(bf[8 + j], h1, l1);
                __nv_bfloat162 ph; ph.x = h0; ph.y = h1;
                __nv_bfloat162 pl; pl.x = l0; pl.y = l1;
                *(__nv_bfloat162*)&Bs_hi[bnb + j][bk0] = ph;
                *(__nv_bfloat162*)&Bs_lo[bnb + j][bk0] = pl;
            }
        }
        __syncthreads();

        if (k0 + BK < K_DIM) { LOADA(k0 + BK); LOADB(k0 + BK); }

#pragma unroll
        for (int ks = 0; ks < 2; ks++) {
            const int kk = ks * 16 + 2 * tg;
            unsigned ah[4][4], al[4][4], bh[4][2], bl[4][2];
#pragma unroll
            for (int mt = 0; mt < 4; mt++) {
                const int r = wr + mt * 16 + g;
                ah[mt][0] = *(const unsigned*)&As_hi[r][kk];
                ah[mt][1] = *(const unsigned*)&As_hi[r + 8][kk];
                ah[mt][2] = *(const unsigned*)&As_hi[r][kk + 8];
                ah[mt][3] = *(const unsigned*)&As_hi[r + 8][kk + 8];
                al[mt][0] = *(const unsigned*)&As_lo[r][kk];
                al[mt][1] = *(const unsigned*)&As_lo[r + 8][kk];
                al[mt][2] = *(const unsigned*)&As_lo[r][kk + 8];
                al[mt][3] = *(const unsigned*)&As_lo[r + 8][kk + 8];
            }
#pragma unroll
            for (int nt = 0; nt < 4; nt++) {
                const int n = wc + nt * 8 + g;
                bh[nt][0] = *(const unsigned*)&Bs_hi[n][kk];
                bh[nt][1] = *(const unsigned*)&Bs_hi[n][kk + 8];
                bl[nt][0] = *(const unsigned*)&Bs_lo[n][kk];
                bl[nt][1] = *(const unsigned*)&Bs_lo[n][kk + 8];
            }
#pragma unroll
            for (int mt = 0; mt < 4; mt++)
#pragma unroll
                for (int nt = 0; nt < 4; nt++) {
                    MMA_BF16(c[mt][nt], ah[mt], bh[nt]);
                    MMA_BF16(c[mt][nt], ah[mt], bl[nt]);
                    MMA_BF16(c[mt][nt], al[mt], bh[nt]);
                }
        }
        __syncthreads();
    }

    // ---- epilogue: bias + RoPE + hi/lo split + scatter ----
#pragma unroll
    for (int nt = 0; nt < 4; nt++) {
        const int col    = col0 + wc + nt * 8 + 2 * tg;   // even
        const int which  = col >> 10;
        const int within = col & 1023;
        const int head   = within >> 6;
        const int dc     = within & 63;                   // even
        const float b0v = bias[col], b1v = bias[col + 1];
        const bool rope = (which < 2) && (dc < 32);
        float invf = 0.f;
        if (rope) invf = (float)exp(-(double)(dc >> 1) * (log(10000.0) / 16.0));
#pragma unroll
        for (int mt = 0; mt < 4; mt++) {
#pragma unroll
            for (int rr = 0; rr < 2; rr++) {
                const int row   = row0 + wr + mt * 16 + g + rr * 8;
                const int batch = row >> 11;
                const int pos   = row & 2047;
                const int bh    = batch * HEADS + head;
                float v0 = c[mt][nt][rr * 2 + 0] + b0v;
                float v1 = c[mt][nt][rr * 2 + 1] + b1v;
                if (rope) {
                    float s, co;
                    sincosf((float)pos * invf, &s, &co);
                    float x = v0, y = v1;
                    v0 = x * co - y * s;
                    v1 = y * co + x * s;
                }
                if (which == 2) {
                    size_t base = ((size_t)bh * HD + dc) * NQ + pos;
                    __nv_bfloat16 h0, l0, h1, l1;
                    cvt_hilo(v0, h0, l0); cvt_hilo(v1, h1, l1);
                    g_vt_hi[base]      = h0; g_vt_lo[base]      = l0;
                    g_vt_hi[base + NQ] = h1; g_vt_lo[base + NQ] = l1;
                } else {
                    if (which == 0) { v0 *= 0.125f; v1 *= 0.125f; }
                    size_t dst = ((size_t)bh * NQ + pos) * HD + dc;
                    __nv_bfloat16 h0, l0, h1, l1;
                    cvt_hilo(v0, h0, l0); cvt_hilo(v1, h1, l1);
                    __nv_bfloat162 ph; ph.x = h0; ph.y = h1;
                    __nv_bfloat162 pl; pl.x = l0; pl.y = l1;
                    if (which == 0) {
                        *(__nv_bfloat162*)(g_q_hi + dst) = ph;
                        *(__nv_bfloat162*)(g_q_lo + dst) = pl;
                    } else {
                        *(__nv_bfloat162*)(g_k_hi + dst) = ph;
                        *(__nv_bfloat162*)(g_k_lo + dst) = pl;
                    }
                }
            }
        }
    }
}

// ---------------------------------------------------------------------------
// Kernel 2: flash attention on tensor cores (bf16 hi/lo, 3-pass).
// 128 q-rows/CTA, 8 warps x 16 rows, key tiles of 64. Q frags in registers.
// ---------------------------------------------------------------------------
#define KSTR 72

__global__ __launch_bounds__(256) void attn_kernel(float* __restrict__ out)
{
    __shared__ __align__(16) __nv_bfloat16 Ks_hi[64][KSTR];
    __shared__ __align__(16) __nv_bfloat16 Ks_lo[64][KSTR];
    __shared__ __align__(16) __nv_bfloat16 Vs_hi[64][KSTR];  // [d][key]
    __shared__ __align__(16) __nv_bfloat16 Vs_lo[64][KSTR];

    const int tid  = threadIdx.x;
    const int lane = tid & 31;
    const int wid  = tid >> 5;
    const int g    = lane >> 2;
    const int tg   = lane & 3;
    const int bh   = blockIdx.y;
    const int q0   = blockIdx.x * 128;
    const int wq   = wid * 16;

    // Q fragments (persistent): rows q0+wq+g / +8, k-steps over d
    unsigned qh[4][4], ql[4][4];
    {
        const size_t r0 = ((size_t)bh * NQ + q0 + wq + g) * HD;
        const size_t r1 = r0 + 8 * HD;
#pragma unroll
        for (int ks = 0; ks < 4; ks++) {
            const int dof = 16 * ks + 2 * tg;
            qh[ks][0] = *(const unsigned*)(g_q_hi + r0 + dof);
            qh[ks][1] = *(const unsigned*)(g_q_hi + r1 + dof);
            qh[ks][2] = *(const unsigned*)(g_q_hi + r0 + dof + 8);
            qh[ks][3] = *(const unsigned*)(g_q_hi + r1 + dof + 8);
            ql[ks][0] = *(const unsigned*)(g_q_lo + r0 + dof);
            ql[ks][1] = *(const unsigned*)(g_q_lo + r1 + dof);
            ql[ks][2] = *(const unsigned*)(g_q_lo + r0 + dof + 8);
            ql[ks][3] = *(const unsigned*)(g_q_lo + r1 + dof + 8);
        }
    }

    const __nv_bfloat16* Kh = g_k_hi + (size_t)bh * NQ * HD;
    const __nv_bfloat16* Kl = g_k_lo + (size_t)bh * NQ * HD;
    const __nv_bfloat16* Vh = g_vt_hi + (size_t)bh * HD * NQ;
    const __nv_bfloat16* Vl = g_vt_lo + (size_t)bh * HD * NQ;

    float m0 = -INFINITY, m1 = -INFINITY, l0 = 0.f, l1 = 0.f;
    float o[8][4];
#pragma unroll
    for (int nt = 0; nt < 8; nt++)
#pragma unroll
        for (int e = 0; e < 4; e++) o[nt][e] = 0.f;

    const int srow = tid >> 2;
    const int sseg = (tid & 3) * 16;

    for (int kt = 0; kt < NQ / 64; kt++) {
        // stage K tile [key][d] and V^T tile [d][key]
        {
            const uint4* s;
            s = (const uint4*)(Kh + ((size_t)(kt * 64 + srow)) * HD + sseg);
            *(uint4*)&Ks_hi[srow][sseg] = s[0]; *(uint4*)&Ks_hi[srow][sseg + 8] = s[1];
            s = (const uint4*)(Kl + ((size_t)(kt * 64 + srow)) * HD + sseg);
            *(uint4*)&Ks_lo[srow][sseg] = s[0]; *(uint4*)&Ks_lo[srow][sseg + 8] = s[1];
            s = (const uint4*)(Vh + (size_t)srow * NQ + kt * 64 + sseg);
            *(uint4*)&Vs_hi[srow][sseg] = s[0]; *(uint4*)&Vs_hi[srow][sseg + 8] = s[1];
            s = (const uint4*)(Vl + (size_t)srow * NQ + kt * 64 + sseg);
            *(uint4*)&Vs_lo[srow][sseg] = s[0]; *(uint4*)&Vs_lo[srow][sseg + 8] = s[1];
        }
        __syncthreads();

        // S = Q K^T  (C cols nt*8+2tg,+1; rows g, g+8)
        float s[8][4];
#pragma unroll
        for (int nt = 0; nt < 8; nt++)
#pragma unroll
            for (int e = 0; e < 4; e++) s[nt][e] = 0.f;
#pragma unroll
        for (int ks = 0; ks < 4; ks++) {
            const int kk = 16 * ks + 2 * tg;
#pragma unroll
            for (int nt = 0; nt < 8; nt++) {
                const int n = nt * 8 + g;
                unsigned bhf[2], blf[2];
                bhf[0] = *(const unsigned*)&Ks_hi[n][kk];
                bhf[1] = *(const unsigned*)&Ks_hi[n][kk + 8];
                blf[0] = *(const unsigned*)&Ks_lo[n][kk];
                blf[1] = *(const unsigned*)&Ks_lo[n][kk + 8];
                MMA_BF16(s[nt], qh[ks], bhf);
                MMA_BF16(s[nt], qh[ks], blf);
                MMA_BF16(s[nt], ql[ks], bhf);
            }
        }

        // online softmax over 64 keys (rows g and g+8)
        float mt0 = -INFINITY, mt1 = -INFINITY;
#pragma unroll
        for (int nt = 0; nt < 8; nt++) {
            mt0 = fmaxf(mt0, fmaxf(s[nt][0], s[nt][1]));
            mt1 = fmaxf(mt1, fmaxf(s[nt][2], s[nt][3]));
        }
        mt0 = fmaxf(mt0, __shfl_xor_sync(0xffffffffu, mt0, 1));
        mt0 = fmaxf(mt0, __shfl_xor_sync(0xffffffffu, mt0, 2));
        mt1 = fmaxf(mt1, __shfl_xor_sync(0xffffffffu, mt1, 1));
        mt1 = fmaxf(mt1, __shfl_xor_sync(0xffffffffu, mt1, 2));
        const float mn0 = fmaxf(m0, mt0);
        const float mn1 = fmaxf(m1, mt1);
        const float a0 = __expf(m0 - mn0);
        const float a1 = __expf(m1 - mn1);
        m0 = mn0; m1 = mn1;
        float rs0 = 0.f, rs1 = 0.f;
#pragma unroll
        for (int nt = 0; nt < 8; nt++) {
            s[nt][0] = __expf(s[nt][0] - mn0);
            s[nt][1] = __expf(s[nt][1] - mn0);
            s[nt][2] = __expf(s[nt][2] - mn1);
            s[nt][3] = __expf(s[nt][3] - mn1);
            rs0 += s[nt][0] + s[nt][1];
            rs1 += s[nt][2] + s[nt][3];
        }
        rs0 += __shfl_xor_sync(0xffffffffu, rs0, 1);
        rs0 += __shfl_xor_sync(0xffffffffu, rs0, 2);
        rs1 += __shfl_xor_sync(0xffffffffu, rs1, 1);
        rs1 += __shfl_xor_sync(0xffffffffu, rs1, 2);
        l0 = l0 * a0 + rs0;
        l1 = l1 * a1 + rs1;
#pragma unroll
        for (int nt = 0; nt < 8; nt++) {
            o[nt][0] *= a0; o[nt][1] *= a0;
            o[nt][2] *= a1; o[nt][3] *= a1;
        }

        // P -> A fragments (register-local): k-step k2 uses n-tiles 2k2, 2k2+1
        unsigned ph[4][4], pl[4][4];
#pragma unroll
        for (int k2 = 0; k2 < 4; k2++) {
#pragma unroll
            for (int half = 0; half < 2; half++) {
                const int nt = 2 * k2 + half;
#pragma unroll
                for (int rr = 0; rr < 2; rr++) {
                    const float u = s[nt][rr * 2 + 0];
                    const float v = s[nt][rr * 2 + 1];
                    __nv_bfloat162 hp = __floats2bfloat162_rn(u, v);
                    __nv_bfloat162 lp = __floats2bfloat162_rn(
                        u - __bfloat162float(hp.x), v - __bfloat162float(hp.y));
                    ph[k2][half * 2 + rr] = *(unsigned*)&hp;
                    pl[k2][half * 2 + rr] = *(unsigned*)&lp;
                }
            }
        }

        // O += P V   (B from V^T: [d][key])
#pragma unroll
        for (int k2 = 0; k2 < 4; k2++) {
            const int kk = 16 * k2 + 2 * tg;
#pragma unroll
            for (int nt = 0; nt < 8; nt++) {
                const int n = nt * 8 + g;
                unsigned bhf[2], blf[2];
                bhf[0] = *(const unsigned*)&Vs_hi[n][kk];
                bhf[1] = *(const unsigned*)&Vs_hi[n][kk + 8];
                blf[0] = *(const unsigned*)&Vs_lo[n][kk];
                blf[1] = *(const unsigned*)&Vs_lo[n][kk + 8];
                MMA_BF16(o[nt], ph[k2], bhf);
                MMA_BF16(o[nt], ph[k2], blf);
                MMA_BF16(o[nt], pl[k2], bhf);
            }
        }
        __syncthreads();
    }

    // epilogue: out[b][pos][head*64 + d]
    const int batch = bh >> 4;
    const int head  = bh & 15;
    const float i0 = 1.f / l0;
    const float i1 = 1.f / l1;
    const int r0 = q0 + wq + g;
    const int r1 = r0 + 8;
#pragma unroll
    for (int nt = 0; nt < 8; nt++) {
        const int d = head * HD + nt * 8 + 2 * tg;
        *(float2*)(out + ((size_t)(batch * NQ + r0)) * DIM + d) =
            make_float2(o[nt][0] * i0, o[nt][1] * i0);
        *(float2*)(out + ((size_t)(batch * NQ + r1)) * DIM + d) =
            make_float2(o[nt][2] * i1, o[nt][3] * i1);
    }
}

// ---------------------------------------------------------------------------
extern "C" void kernel_launch(void* const* d_in, const int* in_sizes, int n_in,
                              void* d_out, int out_size)
{
    const float* x = (const float*)d_in[0];
    const float* w = (const float*)d_in[1];
    const float* b = (const float*)d_in[2];
    float* out = (float*)d_out;

    dim3 g1(N_COLS / BN, M_ROWS / BM);    // (24, 64)
    qkv_gemm_rope<<<g1, 256>>>(x, w, b);

    dim3 g2(NQ / 128, BATCH * HEADS);     // (16, 64)
    attn_kernel<<<g2, 256>>>(out);
}

// round 6
// speedup vs baseline: 2.7962x; 1.4821x over previous
#include <cuda_runtime.h>
#include <math.h>

#define BATCH 4
#define NQ    2048
#define DIM   1024
#define HEADS 16
#define HD    64
#define M_ROWS (BATCH*NQ)
#define N_COLS (3*DIM)
#define K_DIM  DIM
#define BHND ((size_t)BATCH*HEADS*NQ*HD)

// tf32-rounded fp32 planes. Q,K: [bh][n][d]. V: transposed [bh][d][n].
__device__ float g_q[BHND];
__device__ float g_k[BHND];
__device__ float g_vt[BHND];

__device__ __forceinline__ float to_tf32(float x) {
    float r;
    asm("cvt.rna.tf32.f32 %0, %1;" : "=f"(r) : "f"(x));
    return r;
}
__device__ __forceinline__ unsigned tf32_bits(float x) {
    unsigned r;
    asm("cvt.rna.tf32.f32 %0, %1;" : "=r"(r) : "f"(x));
    return r;
}

#define MMA_TF32(C, a0, a1, a2, a3, b0, b1) \
    asm volatile("mma.sync.aligned.m16n8k8.row.col.f32.tf32.tf32.f32 " \
                 "{%0,%1,%2,%3}, {%4,%5,%6,%7}, {%8,%9}, {%0,%1,%2,%3};\n" \
                 : "+f"((C)[0]), "+f"((C)[1]), "+f"((C)[2]), "+f"((C)[3]) \
                 : "r"(a0), "r"(a1), "r"(a2), "r"(a3), "r"(b0), "r"(b1))

#define CP_ASYNC16(dst, src) \
    asm volatile("cp.async.ca.shared.global [%0], [%1], 16;\n" \
                 :: "r"(dst), "l"(src))
#define CP_COMMIT() asm volatile("cp.async.commit_group;\n" ::)
#define CP_WAIT0()  asm volatile("cp.async.wait_group 0;\n" ::)

// ---------------------------------------------------------------------------
// Kernel 1: qkv = x @ W + b via tf32 MMA (1 pass), RoPE, scatter tf32 planes.
// CTA tile 128x128, BK=32, 8 warps (64x32 warp tiles).
// ---------------------------------------------------------------------------
#define BM 128
#define BN 128
#define BK 32
#define APAD 36     // As row stride (floats): bank = 4g+tg, conflict-free
#define BPAD 136    // Bs row stride (floats): bank = 8tg+g, conflict-free

__global__ __launch_bounds__(256, 2) void qkv_gemm_rope(
    const float* __restrict__ X, const float* __restrict__ W,
    const float* __restrict__ bias)
{
    __shared__ float As[BM][APAD];    // [m][k]
    __shared__ float Bs[BK][BPAD];    // [k][n]

    const int tid  = threadIdx.x;
    const int lane = tid & 31;
    const int wid  = tid >> 5;
    const int row0 = blockIdx.y * BM;
    const int col0 = blockIdx.x * BN;
    const int wr = (wid >> 2) * 64;
    const int wc = (wid & 3) * 32;
    const int g  = lane >> 2;
    const int tg = lane & 3;

    float c[4][4][4];
#pragma unroll
    for (int mt = 0; mt < 4; mt++)
#pragma unroll
        for (int nt = 0; nt < 4; nt++)
#pragma unroll
            for (int e = 0; e < 4; e++) c[mt][nt][e] = 0.f;

    const int arow = tid >> 1;
    const int aseg = (tid & 1) * 16;
    const int bk0  = (tid >> 4) * 2;
    const int bn0  = (tid & 15) * 8;

    const float* Ag = X + (size_t)(row0 + arow) * K_DIM + aseg;
    const float* Bg = W + (size_t)bk0 * N_COLS + col0 + bn0;

    float4 abuf[4], bbuf[4];
#define LOADA(kk) { abuf[0] = *(const float4*)(Ag + (kk));      \
                    abuf[1] = *(const float4*)(Ag + (kk) + 4);  \
                    abuf[2] = *(const float4*)(Ag + (kk) + 8);  \
                    abuf[3] = *(const float4*)(Ag + (kk) + 12); }
#define LOADB(kk) { const float* p = Bg + (size_t)(kk) * N_COLS; \
                    bbuf[0] = *(const float4*)p;                  \
                    bbuf[1] = *(const float4*)(p + 4);            \
                    bbuf[2] = *(const float4*)(p + N_COLS);       \
                    bbuf[3] = *(const float4*)(p + N_COLS + 4); }

    LOADA(0); LOADB(0);

    for (int k0 = 0; k0 < K_DIM; k0 += BK) {
        // stage with tf32 rounding
        {
            const float* af = (const float*)abuf;
#pragma unroll
            for (int j = 0; j < 4; j++) {
                float4 v = make_float4(to_tf32(af[4*j]), to_tf32(af[4*j+1]),
                                       to_tf32(af[4*j+2]), to_tf32(af[4*j+3]));
                *(float4*)&As[arow][aseg + 4*j] = v;
            }
            const float* bf = (const float*)bbuf;
#pragma unroll
            for (int r = 0; r < 2; r++)
#pragma unroll
                for (int j = 0; j < 2; j++) {
                    float4 v = make_float4(to_tf32(bf[8*r+4*j]), to_tf32(bf[8*r+4*j+1]),
                                           to_tf32(bf[8*r+4*j+2]), to_tf32(bf[8*r+4*j+3]));
                    *(float4*)&Bs[bk0 + r][bn0 + 4*j] = v;
                }
        }
        __syncthreads();

        if (k0 + BK < K_DIM) { LOADA(k0 + BK); LOADB(k0 + BK); }

#pragma unroll
        for (int ks = 0; ks < 4; ks++) {
            const int kk = 8 * ks;
            unsigned a[4][4], b[4][2];
#pragma unroll
            for (int mt = 0; mt < 4; mt++) {
                const int r = wr + mt * 16 + g;
                a[mt][0] = __float_as_uint(As[r][kk + tg]);
                a[mt][1] = __float_as_uint(As[r + 8][kk + tg]);
                a[mt][2] = __float_as_uint(As[r][kk + tg + 4]);
                a[mt][3] = __float_as_uint(As[r + 8][kk + tg + 4]);
            }
#pragma unroll
            for (int nt = 0; nt < 4; nt++) {
                const int n = wc + nt * 8 + g;
                b[nt][0] = __float_as_uint(Bs[kk + tg][n]);
                b[nt][1] = __float_as_uint(Bs[kk + tg + 4][n]);
            }
#pragma unroll
            for (int mt = 0; mt < 4; mt++)
#pragma unroll
                for (int nt = 0; nt < 4; nt++)
                    MMA_TF32(c[mt][nt], a[mt][0], a[mt][1], a[mt][2], a[mt][3],
                             b[nt][0], b[nt][1]);
        }
        __syncthreads();
    }

    // ---- epilogue: bias + RoPE + tf32 round + scatter ----
#pragma unroll
    for (int nt = 0; nt < 4; nt++) {
        const int col    = col0 + wc + nt * 8 + 2 * tg;   // even
        const int which  = col >> 10;
        const int within = col & 1023;
        const int head   = within >> 6;
        const int dc     = within & 63;                   // even
        const float b0v = bias[col], b1v = bias[col + 1];
        const bool rope = (which < 2) && (dc < 32);
        float invf = 0.f;
        if (rope) invf = (float)exp(-(double)(dc >> 1) * (log(10000.0) / 16.0));
#pragma unroll
        for (int mt = 0; mt < 4; mt++) {
#pragma unroll
            for (int rr = 0; rr < 2; rr++) {
                const int row   = row0 + wr + mt * 16 + g + rr * 8;
                const int batch = row >> 11;
                const int pos   = row & 2047;
                const int bh    = batch * HEADS + head;
                float v0 = c[mt][nt][rr * 2 + 0] + b0v;
                float v1 = c[mt][nt][rr * 2 + 1] + b1v;
                if (rope) {
                    float s, co;
                    sincosf((float)pos * invf, &s, &co);
                    float x = v0, y = v1;
                    v0 = x * co - y * s;
                    v1 = y * co + x * s;
                }
                if (which == 2) {
                    size_t base = ((size_t)bh * HD + dc) * NQ + pos;
                    g_vt[base]      = to_tf32(v0);
                    g_vt[base + NQ] = to_tf32(v1);
                } else {
                    if (which == 0) { v0 *= 0.125f; v1 *= 0.125f; }
                    size_t dst = ((size_t)bh * NQ + pos) * HD + dc;
                    float2 p = make_float2(to_tf32(v0), to_tf32(v1));
                    if (which == 0) *(float2*)(g_q + dst) = p;
                    else            *(float2*)(g_k + dst) = p;
                }
            }
        }
    }
}

// ---------------------------------------------------------------------------
// Kernel 2: flash attention via tf32 MMA (1 pass). 128 q-rows/CTA, 8 warps,
// key tiles of 64, cp.async double-buffered K/V, Q frags in registers.
// ---------------------------------------------------------------------------
#define KST 68   // smem row stride (floats): frag loads bank = 4g+tg

__global__ __launch_bounds__(256, 2) void attn_kernel(float* __restrict__ out)
{
    extern __shared__ float sm[];
    float* Ks = sm;                    // [2][64][KST]
    float* Vs = sm + 2 * 64 * KST;     // [2][64][KST]

    const int tid  = threadIdx.x;
    const int lane = tid & 31;
    const int wid  = tid >> 5;
    const int g    = lane >> 2;
    const int tg   = lane & 3;
    const int bh   = blockIdx.y;
    const int q0   = blockIdx.x * 128;
    const int wq   = wid * 16;

    // persistent Q fragments (already tf32-rounded, pre-scaled)
    unsigned qf[8][4];
    {
        const float* Qg = g_q + ((size_t)bh * NQ + q0 + wq + g) * HD;
        const float* Qg8 = Qg + 8 * HD;
#pragma unroll
        for (int ks = 0; ks < 8; ks++) {
            const int dof = 8 * ks;
            qf[ks][0] = __float_as_uint(Qg [dof + tg]);
            qf[ks][1] = __float_as_uint(Qg8[dof + tg]);
            qf[ks][2] = __float_as_uint(Qg [dof + tg + 4]);
            qf[ks][3] = __float_as_uint(Qg8[dof + tg + 4]);
        }
    }

    const float* Kg = g_k  + (size_t)bh * NQ * HD;
    const float* Vg = g_vt + (size_t)bh * HD * NQ;   // [d][n]

    const int srow = tid & 63;
    const int sseg = (tid >> 6) * 16;

    // stage tile t into buffer buf via cp.async (one commit group)
    auto stage = [&](int t, int buf) {
        const float* kp = Kg + (size_t)(t * 64 + srow) * HD + sseg;
        const float* vp = Vg + (size_t)srow * NQ + t * 64 + sseg;
        unsigned kd = (unsigned)__cvta_generic_to_shared(
                          &Ks[(buf * 64 + srow) * KST + sseg]);
        unsigned vd = (unsigned)__cvta_generic_to_shared(
                          &Vs[(buf * 64 + srow) * KST + sseg]);
#pragma unroll
        for (int j = 0; j < 4; j++) {
            CP_ASYNC16(kd + 16 * j, kp + 4 * j);
            CP_ASYNC16(vd + 16 * j, vp + 4 * j);
        }
        CP_COMMIT();
    };

    stage(0, 0);

    float m0 = -INFINITY, m1 = -INFINITY, l0 = 0.f, l1 = 0.f;
    float o[8][4];
#pragma unroll
    for (int nt = 0; nt < 8; nt++)
#pragma unroll
        for (int e = 0; e < 4; e++) o[nt][e] = 0.f;

    for (int t = 0; t < NQ / 64; t++) {
        CP_WAIT0();
        __syncthreads();
        if (t + 1 < NQ / 64) stage(t + 1, (t + 1) & 1);

        const float* Kb = Ks + (t & 1) * 64 * KST;
        const float* Vb = Vs + (t & 1) * 64 * KST;

        // S = Q K^T
        float s[8][4];
#pragma unroll
        for (int nt = 0; nt < 8; nt++)
#pragma unroll
            for (int e = 0; e < 4; e++) s[nt][e] = 0.f;
#pragma unroll
        for (int ks = 0; ks < 8; ks++) {
            const int kk = 8 * ks;
#pragma unroll
            for (int nt = 0; nt < 8; nt++) {
                const float* kr = Kb + (nt * 8 + g) * KST + kk;
                unsigned b0 = __float_as_uint(kr[tg]);
                unsigned b1 = __float_as_uint(kr[tg + 4]);
                MMA_TF32(s[nt], qf[ks][0], qf[ks][1], qf[ks][2], qf[ks][3], b0, b1);
            }
        }

        // online softmax (rows g, g+8)
        float mt0 = -INFINITY, mt1 = -INFINITY;
#pragma unroll
        for (int nt = 0; nt < 8; nt++) {
            mt0 = fmaxf(mt0, fmaxf(s[nt][0], s[nt][1]));
            mt1 = fmaxf(mt1, fmaxf(s[nt][2], s[nt][3]));
        }
        mt0 = fmaxf(mt0, __shfl_xor_sync(0xffffffffu, mt0, 1));
        mt0 = fmaxf(mt0, __shfl_xor_sync(0xffffffffu, mt0, 2));
        mt1 = fmaxf(mt1, __shfl_xor_sync(0xffffffffu, mt1, 1));
        mt1 = fmaxf(mt1, __shfl_xor_sync(0xffffffffu, mt1, 2));
        const float mn0 = fmaxf(m0, mt0);
        const float mn1 = fmaxf(m1, mt1);
        const float a0 = __expf(m0 - mn0);
        const float a1 = __expf(m1 - mn1);
        m0 = mn0; m1 = mn1;
        float rs0 = 0.f, rs1 = 0.f;
#pragma unroll
        for (int nt = 0; nt < 8; nt++) {
            s[nt][0] = __expf(s[nt][0] - mn0);
            s[nt][1] = __expf(s[nt][1] - mn0);
            s[nt][2] = __expf(s[nt][2] - mn1);
            s[nt][3] = __expf(s[nt][3] - mn1);
            rs0 += s[nt][0] + s[nt][1];
            rs1 += s[nt][2] + s[nt][3];
        }
        rs0 += __shfl_xor_sync(0xffffffffu, rs0, 1);
        rs0 += __shfl_xor_sync(0xffffffffu, rs0, 2);
        rs1 += __shfl_xor_sync(0xffffffffu, rs1, 1);
        rs1 += __shfl_xor_sync(0xffffffffu, rs1, 2);
        l0 = l0 * a0 + rs0;
        l1 = l1 * a1 + rs1;
#pragma unroll
        for (int nt = 0; nt < 8; nt++) {
            o[nt][0] *= a0; o[nt][1] *= a0;
            o[nt][2] *= a1; o[nt][3] *= a1;
        }

        // O += P V : per k-step, build P A-frag by warp shuffle, then 8 MMAs
        const int lane0 = 4 * g + (tg >> 1);
        const int lane2 = lane0 + 2;
        const bool odd = (tg & 1);
#pragma unroll
        for (int ks = 0; ks < 8; ks++) {
            float v00 = __shfl_sync(0xffffffffu, s[ks][0], lane0);
            float v01 = __shfl_sync(0xffffffffu, s[ks][1], lane0);
            float v02 = __shfl_sync(0xffffffffu, s[ks][2], lane0);
            float v03 = __shfl_sync(0xffffffffu, s[ks][3], lane0);
            float v20 = __shfl_sync(0xffffffffu, s[ks][0], lane2);
            float v21 = __shfl_sync(0xffffffffu, s[ks][1], lane2);
            float v22 = __shfl_sync(0xffffffffu, s[ks][2], lane2);
            float v23 = __shfl_sync(0xffffffffu, s[ks][3], lane2);
            unsigned p0 = tf32_bits(odd ? v01 : v00);
            unsigned p1 = tf32_bits(odd ? v03 : v02);
            unsigned p2 = tf32_bits(odd ? v21 : v20);
            unsigned p3 = tf32_bits(odd ? v23 : v22);
            const int kk = 8 * ks;
#pragma unroll
            for (int nt = 0; nt < 8; nt++) {
                const float* vr = Vb + (nt * 8 + g) * KST + kk;
                unsigned b0 = __float_as_uint(vr[tg]);
                unsigned b1 = __float_as_uint(vr[tg + 4]);
                MMA_TF32(o[nt], p0, p1, p2, p3, b0, b1);
            }
        }
    }

    // epilogue
    const int batch = bh >> 4;
    const int head  = bh & 15;
    const float i0 = 1.f / l0;
    const float i1 = 1.f / l1;
    const int r0 = q0 + wq + g;
    const int r1 = r0 + 8;
#pragma unroll
    for (int nt = 0; nt < 8; nt++) {
        const int d = head * HD + nt * 8 + 2 * tg;
        *(float2*)(out + ((size_t)(batch * NQ + r0)) * DIM + d) =
            make_float2(o[nt][0] * i0, o[nt][1] * i0);
        *(float2*)(out + ((size_t)(batch * NQ + r1)) * DIM + d) =
            make_float2(o[nt][2] * i1, o[nt][3] * i1);
    }
}

// ---------------------------------------------------------------------------
extern "C" void kernel_launch(void* const* d_in, const int* in_sizes, int n_in,
                              void* d_out, int out_size)
{
    const float* x = (const float*)d_in[0];
    const float* w = (const float*)d_in[1];
    const float* b = (const float*)d_in[2];
    float* out = (float*)d_out;

    dim3 g1(N_COLS / BN, M_ROWS / BM);    // (24, 64)
    qkv_gemm_rope<<<g1, 256>>>(x, w, b);

    int smem = 4 * 64 * KST * (int)sizeof(float);   // 69632 B
    cudaFuncSetAttribute(attn_kernel, cudaFuncAttributeMaxDynamicSharedMemorySize, smem);
    dim3 g2(NQ / 128, BATCH * HEADS);     // (16, 64)
    attn_kernel<<<g2, 256, smem>>>(out);
}